// round 2
// baseline (speedup 1.0000x reference)
#include <cuda_runtime.h>
#include <cuda_bf16.h>

// Net_60413009985719 on GB300 (sm_103a).
//
// Algebraic collapse: the reference `_lstm_step` sets h_prev = zeros INSIDE the
// step and carries no state across the L=500000 rows, so every row is
// independent, and the head consumes only row L-1. The whole net reduces to:
//   scalar x[L-1] -> layer0 gates (elementwise, G=256)
//                 -> 4x (256x64 matvec + LSTM nonlinearity, f-gate unused)
//                 -> fc(32x64)+ReLU -> {mean(1x32), log_std(1x32), v(16x32->1x16)}
// One block, 256 threads, one launch. Latency-bound; all global loads are
// issued up front (register double-buffer for layer weights, shared staging
// for head weights) so only ONE L2 round trip sits on the critical path.

#define H 64
#define G 256

__device__ __forceinline__ float sigm(float v) {
    return 1.0f / (1.0f + expf(-v));
}

__device__ __forceinline__ float lstm_h(float gi, float gg, float go) {
    float c = sigm(gi) * tanhf(gg);
    return sigm(go) * tanhf(c);
}

__global__ __launch_bounds__(G, 1)
void net_kernel(const float* __restrict__ x, int L,
                const float* __restrict__ Wih0,   // (256,1)
                const float* __restrict__ bih0,   // (256,)
                const float* __restrict__ bhh0,   // (256,)
                const float* __restrict__ Wih,    // (4,256,64)
                const float* __restrict__ bih,    // (4,256)
                const float* __restrict__ bhh,    // (4,256)
                const float* __restrict__ fc_w,   // (32,64)
                const float* __restrict__ fc_b,   // (32,)
                const float* __restrict__ mean_w, // (1,32)
                const float* __restrict__ mean_b, // (1,)
                const float* __restrict__ ls_w,   // (1,32)
                const float* __restrict__ ls_b,   // (1,)
                const float* __restrict__ c1_w,   // (16,32)
                const float* __restrict__ c1_b,   // (16,)
                const float* __restrict__ c2_w,   // (1,16)
                const float* __restrict__ c2_b,   // (1,)
                float* __restrict__ out)          // [mean, log_std, v]
{
    __shared__ float gates[G];
    __shared__ float h[H];
    __shared__ float z[32];
    __shared__ float c1o[16];
    // Head weights staged to shared at kernel entry (loads overlap LSTM chain).
    __shared__ float sfc[32 * H];    // fc_w
    __shared__ float sc1[16 * 32];   // c1_w
    __shared__ float sfcb[32], sc1b[16];
    __shared__ float smw[32], ssw[32], scw[16];
    __shared__ float sconst[3];      // mean_b, ls_b, c2_b

    const int j = threadIdx.x;  // 0..255

    // ---------- issue ALL independent global loads up front ----------
    const float xv    = x[L - 1];
    const float w0    = Wih0[j];
    const float b0    = bih0[j] + bhh0[j];

    // Layer-1 weights (Wih[0]) into register buffer A.
    const float4* __restrict__ W1 =
        reinterpret_cast<const float4*>(Wih) + (size_t)j * (H / 4);
    float4 wA[16], wB[16];
    #pragma unroll
    for (int i = 0; i < 16; i++) wA[i] = W1[i];

    // All 4 layers' bias sums.
    float bsum[4];
    #pragma unroll
    for (int l = 0; l < 4; l++) bsum[l] = bih[l * G + j] + bhh[l * G + j];

    // Stage head weights into shared (independent of everything above).
    {
        // fc_w: 2048 floats = 512 float4; 2 per thread.
        const float4* src = reinterpret_cast<const float4*>(fc_w);
        float4* dst = reinterpret_cast<float4*>(sfc);
        dst[j]       = src[j];
        dst[j + 256] = src[j + 256];
        // c1_w: 512 floats = 128 float4; threads 0..127.
        if (j < 128)
            reinterpret_cast<float4*>(sc1)[j] =
                reinterpret_cast<const float4*>(c1_w)[j];
        // Small tails: threads 128..255.
        int t = j - 128;
        if (t >= 0 && t < 32)        sfcb[t] = fc_b[t];
        else if (t >= 32 && t < 64)  smw[t - 32] = mean_w[t - 32];
        else if (t >= 64 && t < 96)  ssw[t - 64] = ls_w[t - 64];
        else if (t >= 96 && t < 112) sc1b[t - 96] = c1_b[t - 96];
        else if (t >= 112 && t < 128) scw[t - 112] = c2_w[t - 112];
        if (j == 255) { sconst[0] = mean_b[0]; sconst[1] = ls_b[0]; sconst[2] = c2_b[0]; }
    }

    // ---------- layer 0 (elementwise on scalar x[L-1]) ----------
    gates[j] = fmaf(xv, w0, b0);
    __syncthreads();
    if (j < H)
        h[j] = lstm_h(gates[j], gates[2 * H + j], gates[3 * H + j]);
    __syncthreads();

    // ---------- layers 1..4: double-buffered register pipeline ----------
    // DOT(cur): 4-way split accumulators over 16 float4 (chain ~70 cyc).
#define PREFETCH(lnext, buf)                                                   \
    {                                                                          \
        const float4* __restrict__ Wn = reinterpret_cast<const float4*>(Wih)   \
            + ((size_t)(lnext) * G + j) * (H / 4);                             \
        _Pragma("unroll")                                                      \
        for (int i = 0; i < 16; i++) buf[i] = Wn[i];                           \
    }
#define DOT_AND_ACT(lcur, buf)                                                 \
    {                                                                          \
        float a0 = bsum[lcur], a1 = 0.f, a2 = 0.f, a3 = 0.f;                   \
        _Pragma("unroll")                                                      \
        for (int q = 0; q < 4; q++) {                                          \
            _Pragma("unroll")                                                  \
            for (int r = 0; r < 4; r++) {                                      \
                float4 w = buf[q * 4 + r];                                     \
                int k = (q * 4 + r) * 4;                                       \
                float* acc = (r == 0) ? &a0 : (r == 1) ? &a1 :                 \
                             (r == 2) ? &a2 : &a3;                             \
                *acc = fmaf(w.x, h[k + 0], *acc);                              \
                *acc = fmaf(w.y, h[k + 1], *acc);                              \
                *acc = fmaf(w.z, h[k + 2], *acc);                              \
                *acc = fmaf(w.w, h[k + 3], *acc);                              \
            }                                                                  \
        }                                                                      \
        gates[j] = (a0 + a1) + (a2 + a3);                                      \
        __syncthreads();                                                       \
        if (j < H)                                                             \
            h[j] = lstm_h(gates[j], gates[2 * H + j], gates[3 * H + j]);       \
        __syncthreads();                                                       \
    }

    PREFETCH(1, wB);            // layer-2 weights in flight during layer-1 math
    DOT_AND_ACT(0, wA);
    PREFETCH(2, wA);
    DOT_AND_ACT(1, wB);
    PREFETCH(3, wB);
    DOT_AND_ACT(2, wA);
    DOT_AND_ACT(3, wB);
#undef PREFETCH
#undef DOT_AND_ACT

    // ---------- head (all weights already in shared) ----------
    if (j < 32) {
        float a0 = sfcb[j], a1 = 0.f, a2 = 0.f, a3 = 0.f;
        const float* W = sfc + j * H;
        #pragma unroll
        for (int k = 0; k < H; k += 4) {
            a0 = fmaf(W[k + 0], h[k + 0], a0);
            a1 = fmaf(W[k + 1], h[k + 1], a1);
            a2 = fmaf(W[k + 2], h[k + 2], a2);
            a3 = fmaf(W[k + 3], h[k + 3], a3);
        }
        z[j] = fmaxf((a0 + a1) + (a2 + a3), 0.0f);
    }
    __syncthreads();

    if (j < 16) {
        float a0 = sc1b[j], a1 = 0.f;
        const float* W = sc1 + j * 32;
        #pragma unroll
        for (int k = 0; k < 32; k += 2) {
            a0 = fmaf(W[k + 0], z[k + 0], a0);
            a1 = fmaf(W[k + 1], z[k + 1], a1);
        }
        c1o[j] = fmaxf(a0 + a1, 0.0f);
    }
    __syncthreads();

    if (j == 0) {
        float m = sconst[0], s = sconst[1];
        #pragma unroll
        for (int k = 0; k < 32; k++) {
            m = fmaf(smw[k], z[k], m);
            s = fmaf(ssw[k], z[k], s);
        }
        float v = sconst[2];
        #pragma unroll
        for (int k = 0; k < 16; k++) v = fmaf(scw[k], c1o[k], v);
        out[0] = m;
        out[1] = s;
        out[2] = v;
    }
}

extern "C" void kernel_launch(void* const* d_in, const int* in_sizes, int n_in,
                              void* d_out, int out_size)
{
    // metadata order:
    // 0:x 1:Wih0 2:Whh0 3:bih0 4:bhh0 5:Wih 6:Whh 7:bih 8:bhh
    // 9:fc_w 10:fc_b 11:mean_w 12:mean_b 13:ls_w 14:ls_b
    // 15:c1_w 16:c1_b 17:c2_w 18:c2_b
    const float* x      = (const float*)d_in[0];
    const float* Wih0   = (const float*)d_in[1];
    const float* bih0   = (const float*)d_in[3];
    const float* bhh0   = (const float*)d_in[4];
    const float* Wih    = (const float*)d_in[5];
    const float* bih    = (const float*)d_in[7];
    const float* bhh    = (const float*)d_in[8];
    const float* fc_w   = (const float*)d_in[9];
    const float* fc_b   = (const float*)d_in[10];
    const float* mean_w = (const float*)d_in[11];
    const float* mean_b = (const float*)d_in[12];
    const float* ls_w   = (const float*)d_in[13];
    const float* ls_b   = (const float*)d_in[14];
    const float* c1_w   = (const float*)d_in[15];
    const float* c1_b   = (const float*)d_in[16];
    const float* c2_w   = (const float*)d_in[17];
    const float* c2_b   = (const float*)d_in[18];
    const int L = in_sizes[0];

    net_kernel<<<1, G>>>(x, L, Wih0, bih0, bhh0, Wih, bih, bhh,
                         fc_w, fc_b, mean_w, mean_b, ls_w, ls_b,
                         c1_w, c1_b, c2_w, c2_b, (float*)d_out);
}

// round 7
// speedup vs baseline: 1.5394x; 1.5394x over previous
#include <cuda_runtime.h>
#include <cuda_bf16.h>

// Net_60413009985719 on GB300 (sm_103a).
//
// Algebraic collapse: `_lstm_step` zeroes h_prev INSIDE the step (no
// recurrence) and the head consumes only row L-1, so the whole net is one
// scalar x[L-1] through 5 LSTM cells + a tiny MLP head. The f-gate
// (rows 64..127 of each layer's 256 gates) is NEVER used
// (c = sigm(i)*tanh(g); h = sigm(o)*tanh(c)) -> 25% of matvec work deleted.
//
// 384 threads, single block:
//  - 2 threads per live gate row (192 rows: i/g/o), 32-MAC register half-dots,
//    __shfl_xor pair combine
//  - double-buffered register weight prefetch, prefetch issued BEFORE the
//    current layer's FMA block (front-batched LDG)
//  - branch-free MUFU activations (__expf / __fdividef)
//  - layer 0 folded into the activation threads (no barrier, no smem trip)
//  - head weights staged to shared at entry; head runs in warp 0 with
//    __syncwarp; mean/log_std overlap the c1 layer

#define H 64
#define G 256
#define T 384
#define NROW 192        // live gate rows per layer (i,g,o)

__device__ __forceinline__ float fsigm(float x) {
    return __fdividef(1.0f, 1.0f + __expf(-x));
}
__device__ __forceinline__ float ftanh(float x) {
    float e = __expf(2.0f * x);           // 0 / inf at extremes -> exact +-1
    return 1.0f - __fdividef(2.0f, e + 1.0f);
}
__device__ __forceinline__ float lstm_h(float gi, float gg, float go) {
    float c = fsigm(gi) * ftanh(gg);
    return fsigm(go) * ftanh(c);
}

__global__ __launch_bounds__(T, 1)
void net_kernel(const float* __restrict__ x, int L,
                const float* __restrict__ Wih0,   // (256,1)
                const float* __restrict__ bih0,   // (256,)
                const float* __restrict__ bhh0,   // (256,)
                const float* __restrict__ Wih,    // (4,256,64)
                const float* __restrict__ bih,    // (4,256)
                const float* __restrict__ bhh,    // (4,256)
                const float* __restrict__ fc_w,   // (32,64)
                const float* __restrict__ fc_b,   // (32,)
                const float* __restrict__ mean_w, // (1,32)
                const float* __restrict__ mean_b, // (1,)
                const float* __restrict__ ls_w,   // (1,32)
                const float* __restrict__ ls_b,   // (1,)
                const float* __restrict__ c1_w,   // (16,32)
                const float* __restrict__ c1_b,   // (16,)
                const float* __restrict__ c2_w,   // (1,16)
                const float* __restrict__ c2_b,   // (1,)
                float* __restrict__ out)          // [mean, log_std, v]
{
    __shared__ float sg[NROW];       // live gates: [i(64) | g(64) | o(64)]
    __shared__ float h[H];
    __shared__ float zs[32];
    __shared__ float c1s[16];
    __shared__ float sfc[32 * H];    // fc_w staged at entry
    __shared__ float sc1[16 * 32];   // c1_w staged at entry
    __shared__ float sfcb[32], sc1b[16];
    __shared__ float smw[32], ssw[32], scw[16];
    __shared__ float sconst[3];      // mean_b, ls_b, c2_b

    const int t    = threadIdx.x;      // 0..383
    const int tt   = t >> 1;           // live-row index 0..191
    const int half = t & 1;            // which 32-wide half of the dot
    const int type = tt >> 6;          // 0=i, 1=g, 2=o
    const int jrow = tt & 63;          // j within gate type
    // physical gate row in the (256,·) weight layout: i->j, g->128+j, o->192+j
    const int row  = jrow + ((type == 0) ? 0 : (type + 1) * H);

    // ---------------- entry: issue ALL independent global loads ----------------
    const float xv = x[L - 1];

    // Layer-0 scalars for the activation threads (t < 64): all three gates.
    float w0i = 0.f, w0g = 0.f, w0o = 0.f, b0i = 0.f, b0g = 0.f, b0o = 0.f;
    if (t < H) {
        w0i = Wih0[t];           b0i = bih0[t]           + bhh0[t];
        w0g = Wih0[2 * H + t];   b0g = bih0[2 * H + t]   + bhh0[2 * H + t];
        w0o = Wih0[3 * H + t];   b0o = bih0[3 * H + t]   + bhh0[3 * H + t];
    }

    // Per-layer bias for this thread's live row.
    float bias[4];
    #pragma unroll
    for (int l = 0; l < 4; l++) bias[l] = bih[l * G + row] + bhh[l * G + row];

    // Weight double buffers: 8 float4 = this thread's 32-float half-row.
    const float4* __restrict__ Wv = reinterpret_cast<const float4*>(Wih);
    const size_t base = (size_t)row * (H / 4) + (size_t)half * 8;
    const size_t lstride = (size_t)G * (H / 4);
    float4 wA[8], wB[8];
    #pragma unroll
    for (int i = 0; i < 8; i++) wA[i] = Wv[base + i];             // layer 1
    #pragma unroll
    for (int i = 0; i < 8; i++) wB[i] = Wv[lstride + base + i];   // layer 2

    // Head staging (independent; overlaps the whole LSTM chain).
    {
        const float4* srcf = reinterpret_cast<const float4*>(fc_w);
        float4* dstf = reinterpret_cast<float4*>(sfc);
        dstf[t] = srcf[t];                       // 384 of 512 float4
        if (t < 128) dstf[384 + t] = srcf[384 + t];
        if (t >= 128 && t < 256)
            reinterpret_cast<float4*>(sc1)[t - 128] =
                reinterpret_cast<const float4*>(c1_w)[t - 128];
        int t2 = t - 256;                        // threads 256..383 for tails
        if (t2 >= 0 && t2 < 32)          sfcb[t2]      = fc_b[t2];
        else if (t2 >= 32 && t2 < 64)    smw[t2 - 32]  = mean_w[t2 - 32];
        else if (t2 >= 64 && t2 < 96)    ssw[t2 - 64]  = ls_w[t2 - 64];
        else if (t2 >= 96 && t2 < 112)   sc1b[t2 - 96] = c1_b[t2 - 96];
        else if (t2 >= 112 && t2 < 128)  scw[t2 - 112] = c2_w[t2 - 112];
        if (t == 383) { sconst[0] = mean_b[0]; sconst[1] = ls_b[0]; sconst[2] = c2_b[0]; }
    }

    // ---------------- layer 0: computed locally by the h-threads ----------------
    if (t < H) {
        float gi = fmaf(xv, w0i, b0i);
        float gg = fmaf(xv, w0g, b0g);
        float go = fmaf(xv, w0o, b0o);
        h[t] = lstm_h(gi, gg, go);
    }
    __syncthreads();

    // ---------------- layers 1..4 ----------------
    // Prefetch of layer l+1 is issued FIRST (independent of h), then the
    // current layer's 32-MAC half-dot, pair-combined via shfl.
#define DOT_LAYER(buf, lcur, DO_PREF, lnext, nbuf)                             \
    {                                                                          \
        if (DO_PREF) {                                                         \
            _Pragma("unroll")                                                  \
            for (int i = 0; i < 8; i++)                                        \
                nbuf[i] = Wv[(size_t)(lnext) * lstride + base + i];            \
        }                                                                      \
        const float* __restrict__ hh = h + half * 32;                          \
        float a0 = 0.f, a1 = 0.f, a2 = 0.f, a3 = 0.f;                          \
        _Pragma("unroll")                                                      \
        for (int i = 0; i < 8; i++) {                                          \
            float4 w = buf[i];                                                 \
            int k = i * 4;                                                     \
            a0 = fmaf(w.x, hh[k + 0], a0);                                     \
            a1 = fmaf(w.y, hh[k + 1], a1);                                     \
            a2 = fmaf(w.z, hh[k + 2], a2);                                     \
            a3 = fmaf(w.w, hh[k + 3], a3);                                     \
        }                                                                      \
        float p = (a0 + a1) + (a2 + a3);                                       \
        p += __shfl_xor_sync(0xffffffffu, p, 1);                               \
        if (!half) sg[tt] = p + bias[lcur];                                    \
        __syncthreads();                                                       \
        if (t < H) h[t] = lstm_h(sg[t], sg[H + t], sg[2 * H + t]);             \
        __syncthreads();                                                       \
    }

    DOT_LAYER(wA, 0, 1, 2, wA);   // consume W[0]; W[2] load in flight -> wA
    DOT_LAYER(wB, 1, 1, 3, wB);   // consume W[1]; W[3] load in flight -> wB
    DOT_LAYER(wA, 2, 0, 0, wA);
    DOT_LAYER(wB, 3, 0, 0, wB);
#undef DOT_LAYER

    // ---------------- head: entirely in warp 0 ----------------
    if (t < 32) {
        const float* __restrict__ W = sfc + t * H;
        float a0 = sfcb[t], a1 = 0.f, a2 = 0.f, a3 = 0.f;
        #pragma unroll
        for (int k = 0; k < H; k += 4) {
            a0 = fmaf(W[k + 0], h[k + 0], a0);
            a1 = fmaf(W[k + 1], h[k + 1], a1);
            a2 = fmaf(W[k + 2], h[k + 2], a2);
            a3 = fmaf(W[k + 3], h[k + 3], a3);
        }
        zs[t] = fmaxf((a0 + a1) + (a2 + a3), 0.0f);
        __syncwarp();

        if (t < 16) {                       // c1 layer
            const float* __restrict__ C = sc1 + t * 32;
            float b0_ = sc1b[t], b1_ = 0.f;
            #pragma unroll
            for (int k = 0; k < 32; k += 2) {
                b0_ = fmaf(C[k + 0], zs[k + 0], b0_);
                b1_ = fmaf(C[k + 1], zs[k + 1], b1_);
            }
            c1s[t] = fmaxf(b0_ + b1_, 0.0f);
        } else if (t == 16) {               // mean (concurrent with c1)
            float m0 = sconst[0], m1 = 0.f;
            #pragma unroll
            for (int k = 0; k < 32; k += 2) {
                m0 = fmaf(smw[k + 0], zs[k + 0], m0);
                m1 = fmaf(smw[k + 1], zs[k + 1], m1);
            }
            out[0] = m0 + m1;
        } else if (t == 17) {               // log_std (concurrent with c1)
            float s0 = sconst[1], s1 = 0.f;
            #pragma unroll
            for (int k = 0; k < 32; k += 2) {
                s0 = fmaf(ssw[k + 0], zs[k + 0], s0);
                s1 = fmaf(ssw[k + 1], zs[k + 1], s1);
            }
            out[1] = s0 + s1;
        }
        __syncwarp();

        if (t == 0) {                       // v
            float v0 = sconst[2], v1 = 0.f;
            #pragma unroll
            for (int k = 0; k < 16; k += 2) {
                v0 = fmaf(scw[k + 0], c1s[k + 0], v0);
                v1 = fmaf(scw[k + 1], c1s[k + 1], v1);
            }
            out[2] = v0 + v1;
        }
    }
}

extern "C" void kernel_launch(void* const* d_in, const int* in_sizes, int n_in,
                              void* d_out, int out_size)
{
    // metadata order:
    // 0:x 1:Wih0 2:Whh0 3:bih0 4:bhh0 5:Wih 6:Whh 7:bih 8:bhh
    // 9:fc_w 10:fc_b 11:mean_w 12:mean_b 13:ls_w 14:ls_b
    // 15:c1_w 16:c1_b 17:c2_w 18:c2_b
    const float* x      = (const float*)d_in[0];
    const float* Wih0   = (const float*)d_in[1];
    const float* bih0   = (const float*)d_in[3];
    const float* bhh0   = (const float*)d_in[4];
    const float* Wih    = (const float*)d_in[5];
    const float* bih    = (const float*)d_in[7];
    const float* bhh    = (const float*)d_in[8];
    const float* fc_w   = (const float*)d_in[9];
    const float* fc_b   = (const float*)d_in[10];
    const float* mean_w = (const float*)d_in[11];
    const float* mean_b = (const float*)d_in[12];
    const float* ls_w   = (const float*)d_in[13];
    const float* ls_b   = (const float*)d_in[14];
    const float* c1_w   = (const float*)d_in[15];
    const float* c1_b   = (const float*)d_in[16];
    const float* c2_w   = (const float*)d_in[17];
    const float* c2_b   = (const float*)d_in[18];
    const int L = in_sizes[0];

    net_kernel<<<1, T>>>(x, L, Wih0, bih0, bhh0, Wih, bih, bhh,
                         fc_w, fc_b, mean_w, mean_b, ls_w, ls_b,
                         c1_w, c1_b, c2_w, c2_b, (float*)d_out);
}